// round 2
// baseline (speedup 1.0000x reference)
#include <cuda_runtime.h>
#include <math.h>

#define NROWS   65536
#define DDIM    64
#define TILE    64
#define NBLK    1024          /* NROWS / TILE */
#define NTHR    256
#define NSTEPS  128
#define TSZ     4096          /* TILE * DDIM floats */
#define SMEM_FLOATS (TSZ + 64 + TSZ + TSZ + 6 * TSZ)
#define SMEM_BYTES  (SMEM_FLOATS * 4)

/* ---------------- persistent device state (no allocations) ---------------- */
struct Scal { float t, h, h_eff; int done, sel; };
__device__ Scal   g_scal;
__device__ float  g_Ya[NROWS * DDIM];
__device__ float  g_Yb[NROWS * DDIM];
__device__ float  g_Ka[NROWS * DDIM];
__device__ float  g_Kb[NROWS * DDIM];
__device__ double g_part[NBLK];

/* Dormand-Prince A coefficients (exact float32 of rationals) */
__constant__ float cA[6][6] = {
  { (float)(1.0/5.0), 0.f, 0.f, 0.f, 0.f, 0.f },
  { (float)(3.0/40.0), (float)(9.0/40.0), 0.f, 0.f, 0.f, 0.f },
  { (float)(44.0/45.0), (float)(-56.0/15.0), (float)(32.0/9.0), 0.f, 0.f, 0.f },
  { (float)(19372.0/6561.0), (float)(-25360.0/2187.0), (float)(64448.0/6561.0), (float)(-212.0/729.0), 0.f, 0.f },
  { (float)(9017.0/3168.0), (float)(-355.0/33.0), (float)(46732.0/5247.0), (float)(49.0/176.0), (float)(-5103.0/18656.0), 0.f },
  { (float)(35.0/384.0), 0.f, (float)(500.0/1113.0), (float)(125.0/192.0), (float)(-2187.0/6784.0), (float)(11.0/84.0) },
};

struct F4 { float v[4]; };
__device__ __forceinline__ F4 ld4(const float* p) {
  float4 t = *(const float4*)p; F4 r; r.v[0]=t.x; r.v[1]=t.y; r.v[2]=t.z; r.v[3]=t.w; return r;
}
__device__ __forceinline__ void st4(float* p, const F4 a) {
  float4 t; t.x=a.v[0]; t.y=a.v[1]; t.z=a.v[2]; t.w=a.v[3]; *(float4*)p = t;
}

/* 64x64x64 tile GEMM: acc[i][j] = sum_k yi[rb4+i][k] * W[cb*4+j][k].
   k loop staggered by cb so both SMEM streams are bank-conflict-free. */
__device__ __forceinline__ void gemm64(const float* __restrict__ syi,
                                       const float* __restrict__ sW,
                                       int rb4, int cb, float acc[4][4]) {
#pragma unroll
  for (int i = 0; i < 4; ++i)
#pragma unroll
    for (int j = 0; j < 4; ++j) acc[i][j] = 0.f;
#pragma unroll 4
  for (int k4 = 0; k4 < 16; ++k4) {
    const int kk = ((k4 + cb) & 15) * 4;
    F4 a[4], w[4];
#pragma unroll
    for (int i = 0; i < 4; ++i) a[i] = ld4(&syi[(rb4 + i) * DDIM + kk]);
#pragma unroll
    for (int j = 0; j < 4; ++j) w[j] = ld4(&sW[(cb * 4 + j) * DDIM + kk]);
#pragma unroll
    for (int i = 0; i < 4; ++i)
#pragma unroll
      for (int j = 0; j < 4; ++j)
#pragma unroll
        for (int e = 0; e < 4; ++e)
          acc[i][j] = fmaf(a[i].v[e], w[j].v[e], acc[i][j]);
  }
}

/* ---------------- init scalars ---------------- */
__global__ void init_kernel() {
  g_scal.t = 0.0f;
  g_scal.h = 0.01f;
  g_scal.h_eff = 0.01f;  /* min(0.01, max(5-0, 1e-12)) */
  g_scal.done = 0;
  g_scal.sel = 0;
}

/* ---------------- prologue: Ya = x, Ka = k1 = f(x) ---------------- */
__global__ void __launch_bounds__(NTHR) k1_kernel(const float* __restrict__ x,
                                                  const float* __restrict__ W,
                                                  const float* __restrict__ b) {
  __shared__ float sW[TSZ];
  __shared__ float sy[TSZ];
  __shared__ float sb[DDIM];
  const int tid = threadIdx.x;
  const size_t base = (size_t)blockIdx.x * TSZ;
  for (int i = tid; i < TSZ / 4; i += NTHR) st4(&sW[i * 4], ld4(&W[i * 4]));
  if (tid < 16) st4(&sb[tid * 4], ld4(&b[tid * 4]));
  for (int i = tid; i < TSZ / 4; i += NTHR) {
    F4 v = ld4(&x[base + i * 4]);
    st4(&sy[i * 4], v);
    st4(&g_Ya[base + i * 4], v);
  }
  __syncthreads();
  const int rb4 = (tid >> 4) * 4, cb = tid & 15;
  float acc[4][4];
  gemm64(sy, sW, rb4, cb, acc);
  const F4 bb = ld4(&sb[cb * 4]);
#pragma unroll
  for (int i = 0; i < 4; ++i) {
    F4 kv;
#pragma unroll
    for (int j = 0; j < 4; ++j) kv.v[j] = sinf(-(acc[i][j] + bb.v[j]));
    st4(&g_Ka[base + (rb4 + i) * DDIM + cb * 4], kv);
  }
}

/* ---------------- one full RK step for a 64-row tile ---------------- */
__global__ void __launch_bounds__(NTHR, 1) step_kernel(const float* __restrict__ W,
                                                       const float* __restrict__ b) {
  if (g_scal.done) return;
  const float h   = g_scal.h_eff;
  const int   sel = g_scal.sel;
  const float* __restrict__ Yg = sel ? g_Yb : g_Ya;
  const float* __restrict__ Kg = sel ? g_Kb : g_Ka;
  float* __restrict__ Yo = sel ? g_Ya : g_Yb;
  float* __restrict__ Ko = sel ? g_Ka : g_Kb;

  extern __shared__ float sm[];
  float* sW  = sm;               /* 4096 : W[c][k]            */
  float* sb  = sW + TSZ;         /* 64                        */
  float* sy  = sb + 64;          /* 4096 : y tile             */
  float* syi = sy + TSZ;         /* 4096 : stage input / y5   */
  float* sk  = syi + TSZ;        /* 6*4096 : k1..k6           */

  const int tid = threadIdx.x;
  const size_t base = (size_t)blockIdx.x * TSZ;

  for (int i = tid; i < TSZ / 4; i += NTHR) st4(&sW[i * 4], ld4(&W[i * 4]));
  if (tid < 16) st4(&sb[tid * 4], ld4(&b[tid * 4]));
  for (int i = tid; i < TSZ / 4; i += NTHR) st4(&sy[i * 4], ld4(&Yg[base + i * 4]));
  for (int i = tid; i < TSZ / 4; i += NTHR) st4(&sk[i * 4], ld4(&Kg[base + i * 4])); /* k1 (FSAL) */
  __syncthreads();

  const int rb4 = (tid >> 4) * 4, cb = tid & 15;
  const F4 bb = ld4(&sb[cb * 4]);
  float k7r[4][4];

#pragma unroll
  for (int st = 1; st <= 6; ++st) {
    /* yi = y + h * sum_{j<st} A[st-1][j] * k_j ; stage-6 yi == y5 (FSAL) */
    for (int i = tid; i < TSZ / 4; i += NTHR) {
      F4 yv = ld4(&sy[i * 4]);
      F4 s;
      {
        F4 k0 = ld4(&sk[i * 4]);
#pragma unroll
        for (int e = 0; e < 4; ++e) s.v[e] = cA[st - 1][0] * k0.v[e];
      }
#pragma unroll
      for (int j = 1; j < 6; ++j) {
        if (j < st) {
          F4 kv = ld4(&sk[j * TSZ + i * 4]);
#pragma unroll
          for (int e = 0; e < 4; ++e) s.v[e] = fmaf(cA[st - 1][j], kv.v[e], s.v[e]);
        }
      }
      F4 yiv;
#pragma unroll
      for (int e = 0; e < 4; ++e) yiv.v[e] = fmaf(h, s.v[e], yv.v[e]);
      st4(&syi[i * 4], yiv);
      if (st == 6) st4(&Yo[base + i * 4], yiv);  /* y5 candidate out */
    }
    __syncthreads();

    float acc[4][4];
    gemm64(syi, sW, rb4, cb, acc);

    if (st < 6) {
#pragma unroll
      for (int i = 0; i < 4; ++i) {
        F4 kv;
#pragma unroll
        for (int j = 0; j < 4; ++j) kv.v[j] = sinf(-(acc[i][j] + bb.v[j]));
        st4(&sk[st * TSZ + (rb4 + i) * DDIM + cb * 4], kv);
      }
      __syncthreads();
    } else {
#pragma unroll
      for (int i = 0; i < 4; ++i)
#pragma unroll
        for (int j = 0; j < 4; ++j) k7r[i][j] = sinf(-(acc[i][j] + bb.v[j]));
    }
  }

  /* err = h*(E0 k1 + E2 k3 + E3 k4 + E4 k5 + E5 k6 + E6 k7); E1 = 0.
     scale = ATOL + RTOL*max(|y|,|y5|); accumulate (err/scale)^2. */
  const float E0 = (float)(71.0 / 57600.0);
  const float E2 = (float)(-71.0 / 16695.0);
  const float E3 = (float)(71.0 / 1920.0);
  const float E4 = (float)(-17253.0 / 339200.0);
  const float E5 = (float)(22.0 / 525.0);
  const float E6 = (float)(-1.0 / 40.0);
  const float ATOL = 1e-5f, RTOL = 1e-5f;

  double lsum = 0.0;
#pragma unroll
  for (int i = 0; i < 4; ++i) {
    const int o = (rb4 + i) * DDIM + cb * 4;
    F4 k1v = ld4(&sk[o]);
    F4 k3v = ld4(&sk[2 * TSZ + o]);
    F4 k4v = ld4(&sk[3 * TSZ + o]);
    F4 k5v = ld4(&sk[4 * TSZ + o]);
    F4 k6v = ld4(&sk[5 * TSZ + o]);
    F4 y5v = ld4(&syi[o]);
    F4 yv  = ld4(&sy[o]);
    F4 k7v;
#pragma unroll
    for (int j = 0; j < 4; ++j) k7v.v[j] = k7r[i][j];
    /* FSAL: store k7 as next step's k1 */
    st4(&Ko[base + o], k7v);
#pragma unroll
    for (int j = 0; j < 4; ++j) {
      float e = E0 * k1v.v[j];
      e = fmaf(E2, k3v.v[j], e);
      e = fmaf(E3, k4v.v[j], e);
      e = fmaf(E4, k5v.v[j], e);
      e = fmaf(E5, k6v.v[j], e);
      e = fmaf(E6, k7v.v[j], e);
      e *= h;
      float scale = fmaf(RTOL, fmaxf(fabsf(yv.v[j]), fabsf(y5v.v[j])), ATOL);
      float r = e / scale;
      lsum += (double)(r * r);
    }
  }

  /* deterministic block reduction of lsum (reuse smem as doubles) */
  __syncthreads();
  double* sd = (double*)sm;
  sd[tid] = lsum;
  __syncthreads();
#pragma unroll
  for (int off = NTHR / 2; off > 0; off >>= 1) {
    if (tid < off) sd[tid] += sd[tid + off];
    __syncthreads();
  }
  if (tid == 0) g_part[blockIdx.x] = sd[0];
}

/* ---------------- accept/reject + step-size control ---------------- */
__global__ void control_kernel() {
  __shared__ double sd[256];
  if (g_scal.done) return;
  double s = 0.0;
  for (int i = threadIdx.x; i < NBLK; i += 256) s += g_part[i];
  sd[threadIdx.x] = s;
  __syncthreads();
#pragma unroll
  for (int off = 128; off > 0; off >>= 1) {
    if (threadIdx.x < off) sd[threadIdx.x] += sd[threadIdx.x + off];
    __syncthreads();
  }
  if (threadIdx.x == 0) {
    const double mean = sd[0] / (double)((size_t)NROWS * DDIM);
    const float err_norm = sqrtf((float)mean);
    const float h_eff = g_scal.h_eff;
    const int accept = (err_norm <= 1.0f);
    if (accept) {
      g_scal.t += h_eff;
      g_scal.sel ^= 1;
    }
    float factor = 0.9f * powf(fmaxf(err_norm, 1e-10f), -0.2f);
    factor = fminf(fmaxf(factor, 0.2f), 10.0f);
    const float h = h_eff * factor;
    g_scal.h = h;
    const float remaining = 5.0f - g_scal.t;
    g_scal.done = (remaining <= 0.0f) ? 1 : 0;
    g_scal.h_eff = fminf(h, fmaxf(remaining, 1e-12f));
  }
}

/* ---------------- write selected buffer to output ---------------- */
__global__ void finalize_kernel(float* __restrict__ out) {
  const float* __restrict__ Y = g_scal.sel ? g_Yb : g_Ya;
  const size_t n4 = (size_t)NROWS * DDIM / 4;
  for (size_t i = (size_t)blockIdx.x * blockDim.x + threadIdx.x; i < n4;
       i += (size_t)gridDim.x * blockDim.x) {
    st4(&out[i * 4], ld4(&Y[i * 4]));
  }
}

extern "C" void kernel_launch(void* const* d_in, const int* in_sizes, int n_in,
                              void* d_out, int out_size) {
  const float* x = (const float*)d_in[0];
  const float* W = (const float*)d_in[1];
  const float* b = (const float*)d_in[2];
  float* out = (float*)d_out;

  cudaFuncSetAttribute(step_kernel, cudaFuncAttributeMaxDynamicSharedMemorySize, SMEM_BYTES);

  init_kernel<<<1, 1>>>();
  k1_kernel<<<NBLK, NTHR>>>(x, W, b);
  for (int s = 0; s < NSTEPS; ++s) {
    step_kernel<<<NBLK, NTHR, SMEM_BYTES>>>(W, b);
    control_kernel<<<1, 256>>>();
  }
  finalize_kernel<<<512, 256>>>(out);
}

// round 3
// speedup vs baseline: 1.1623x; 1.1623x over previous
#include <cuda_runtime.h>
#include <math.h>

#define NROWS   65536
#define DDIM    64
#define NTILE   1024          /* NROWS / 64 */
#define PBLK    148           /* persistent blocks, 1 per SM, all resident */
#define NTHR    256
#define NSTEPS  128
#define TSZ     4096          /* 64*64 floats per tile */

/* shared memory layout (float offsets) */
#define OFF_SB  0             /* 64  : bias               */
#define OFF_CTL 64            /* 16  : control broadcast  */
#define OFF_W2  80            /* 4096: W repacked (k-pair major) */
#define OFF_SY  4176          /* 4096: y tile   (also reused as 256 doubles for reduce) */
#define OFF_SYI 8272          /* 4096: stage input / y5   */
#define OFF_SK  12368         /* 6*4096: k1..k6           */
#define SMEM_FLOATS 36944
#define SMEM_BYTES  (SMEM_FLOATS * 4)

typedef unsigned long long ull;

/* ---------------- persistent device state (no allocations) ---------------- */
__device__ float  g_Ya[NROWS * DDIM];
__device__ float  g_Yb[NROWS * DDIM];
__device__ float  g_Ka[NROWS * DDIM];
__device__ float  g_Kb[NROWS * DDIM];
__device__ double g_part[2][PBLK];
__device__ unsigned g_count;
__device__ unsigned g_release;

/* Dormand-Prince A coefficients (exact float32 of rationals) */
__constant__ float cA[6][6] = {
  { (float)(1.0/5.0), 0.f, 0.f, 0.f, 0.f, 0.f },
  { (float)(3.0/40.0), (float)(9.0/40.0), 0.f, 0.f, 0.f, 0.f },
  { (float)(44.0/45.0), (float)(-56.0/15.0), (float)(32.0/9.0), 0.f, 0.f, 0.f },
  { (float)(19372.0/6561.0), (float)(-25360.0/2187.0), (float)(64448.0/6561.0), (float)(-212.0/729.0), 0.f, 0.f },
  { (float)(9017.0/3168.0), (float)(-355.0/33.0), (float)(46732.0/5247.0), (float)(49.0/176.0), (float)(-5103.0/18656.0), 0.f },
  { (float)(35.0/384.0), 0.f, (float)(500.0/1113.0), (float)(125.0/192.0), (float)(-2187.0/6784.0), (float)(11.0/84.0) },
};

struct F4 { float v[4]; };
__device__ __forceinline__ F4 ld4(const float* p) {
  float4 t = *(const float4*)p; F4 r; r.v[0]=t.x; r.v[1]=t.y; r.v[2]=t.z; r.v[3]=t.w; return r;
}
__device__ __forceinline__ void st4(float* p, const F4 a) {
  float4 t; t.x=a.v[0]; t.y=a.v[1]; t.z=a.v[2]; t.w=a.v[3]; *(float4*)p = t;
}

/* packed fp32x2 FMA (Blackwell): lanes accumulate even-k / odd-k partials */
__device__ __forceinline__ ull fma2(ull a, ull b, ull c) {
  ull d;
  asm("fma.rn.f32x2 %0, %1, %2, %3;" : "=l"(d) : "l"(a), "l"(b), "l"(c));
  return d;
}
__device__ __forceinline__ void unpack2(ull v, float& lo, float& hi) {
  asm("mov.b64 {%0, %1}, %2;" : "=f"(lo), "=f"(hi) : "l"(v));
}

/* 64x64x64 tile GEMM via fma.rn.f32x2, k-pair packed.
   acc[i][j] = sum_k a[rb4+i][k] * W[cb*4+j][k]
   sW2 layout: for k-pair k2 (0..31):
     sW2[k2*128 +      cb*4 + 0..3] = {W[4cb][2k2],W[4cb][2k2+1],W[4cb+1][2k2],W[4cb+1][2k2+1]}
     sW2[k2*128 + 64 + cb*4 + 0..3] = same for j=4cb+2, 4cb+3
   -> each 16-thread phase reads 256B contiguous (2 conflict-free wavefronts);
      a-loads broadcast across the 16 cb threads. */
__device__ __forceinline__ void gemm64_f2(const float* __restrict__ sa,
                                          const float* __restrict__ sW2,
                                          int rb4, int cb, float accf[4][4]) {
  ull acc[4][4];
#pragma unroll
  for (int i = 0; i < 4; ++i)
#pragma unroll
    for (int j = 0; j < 4; ++j) acc[i][j] = 0ull;

#pragma unroll
  for (int k4 = 0; k4 < 16; ++k4) {
    ulonglong2 av[4];
#pragma unroll
    for (int i = 0; i < 4; ++i)
      av[i] = *(const ulonglong2*)(sa + (rb4 + i) * DDIM + k4 * 4);
#pragma unroll
    for (int hh = 0; hh < 2; ++hh) {
      const int k2 = k4 * 2 + hh;
      ulonglong2 w01 = *(const ulonglong2*)(sW2 + k2 * 128 + cb * 4);
      ulonglong2 w23 = *(const ulonglong2*)(sW2 + k2 * 128 + 64 + cb * 4);
#pragma unroll
      for (int i = 0; i < 4; ++i) {
        ull a = hh ? av[i].y : av[i].x;
        acc[i][0] = fma2(a, w01.x, acc[i][0]);
        acc[i][1] = fma2(a, w01.y, acc[i][1]);
        acc[i][2] = fma2(a, w23.x, acc[i][2]);
        acc[i][3] = fma2(a, w23.y, acc[i][3]);
      }
    }
  }
#pragma unroll
  for (int i = 0; i < 4; ++i)
#pragma unroll
    for (int j = 0; j < 4; ++j) {
      float lo, hi; unpack2(acc[i][j], lo, hi);
      accf[i][j] = lo + hi;
    }
}

__global__ void init_kernel() { g_count = 0u; g_release = 0u; }

/* ---------------- the whole solve in one persistent kernel ---------------- */
__global__ void __launch_bounds__(NTHR, 1) ode_kernel(const float* __restrict__ x,
                                                      const float* __restrict__ W,
                                                      const float* __restrict__ b,
                                                      float* __restrict__ out) {
  extern __shared__ float sm[];
  float* sb  = sm + OFF_SB;
  float* sW2 = sm + OFF_W2;
  float* sy  = sm + OFF_SY;
  float* syi = sm + OFF_SYI;
  float* sk  = sm + OFF_SK;

  const int tid = threadIdx.x, bid = blockIdx.x;
  const int rb4 = (tid >> 4) << 2;   /* row group base (0,4,...,60) */
  const int cb  = tid & 15;          /* col group (j base = cb*4)   */

  if (tid < 16) st4(&sb[tid * 4], ld4(&b[tid * 4]));
  /* repack W into k-pair-major layout */
  for (int p = tid; p < 2048; p += NTHR) {
    const int k2 = p >> 6, j = p & 63;
    const int cbb = j >> 2, jr = j & 3;
    const int pos = k2 * 128 + ((jr >= 2) ? 64 : 0) + cbb * 4 + (jr & 1) * 2;
    sW2[pos]     = W[j * DDIM + 2 * k2];
    sW2[pos + 1] = W[j * DDIM + 2 * k2 + 1];
  }
  __syncthreads();
  const F4 bb = ld4(&sb[cb * 4]);

  /* prologue: Ya = x ; Ka = k1 = f(x).  Tiles are block-owned (bid, bid+148, ...). */
  for (int tile = bid; tile < NTILE; tile += PBLK) {
    const size_t base = (size_t)tile * TSZ;
    for (int i = tid; i < TSZ / 4; i += NTHR) {
      F4 v = ld4(&x[base + i * 4]);
      st4(&sy[i * 4], v);
      st4(&g_Ya[base + i * 4], v);
    }
    __syncthreads();
    float acc[4][4];
    gemm64_f2(sy, sW2, rb4, cb, acc);
#pragma unroll
    for (int i = 0; i < 4; ++i) {
      F4 kv;
#pragma unroll
      for (int j = 0; j < 4; ++j) kv.v[j] = sinf(-(acc[i][j] + bb.v[j]));
      st4(&g_Ka[base + (rb4 + i) * DDIM + cb * 4], kv);
    }
    __syncthreads();
  }

  float t = 0.0f, h = 0.01f, h_eff = 0.01f;
  int sel = 0, done = 0;
  unsigned nbar = 0;

  const float E0 = (float)(71.0 / 57600.0);
  const float E2 = (float)(-71.0 / 16695.0);
  const float E3 = (float)(71.0 / 1920.0);
  const float E4 = (float)(-17253.0 / 339200.0);
  const float E5 = (float)(22.0 / 525.0);
  const float E6 = (float)(-1.0 / 40.0);
  const float ATOL = 1e-5f, RTOL = 1e-5f;

  for (int step = 0; step < NSTEPS; ++step) {
    if (done) break;
    const float* __restrict__ Yg = sel ? g_Yb : g_Ya;
    const float* __restrict__ Kg = sel ? g_Kb : g_Ka;
    float* __restrict__ Yo = sel ? g_Ya : g_Yb;
    float* __restrict__ Ko = sel ? g_Ka : g_Kb;

    double lsum = 0.0;
    for (int tile = bid; tile < NTILE; tile += PBLK) {
      const size_t base = (size_t)tile * TSZ;
      for (int i = tid; i < TSZ / 4; i += NTHR) st4(&sy[i * 4], ld4(&Yg[base + i * 4]));
      for (int i = tid; i < TSZ / 4; i += NTHR) st4(&sk[i * 4], ld4(&Kg[base + i * 4]));
      __syncthreads();

      float k7r[4][4];
#pragma unroll
      for (int st = 1; st <= 6; ++st) {
        /* yi = y + h_eff * sum_{j<st} A[st-1][j] k_j ; stage 6 yi == y5 (FSAL) */
        for (int i = tid; i < TSZ / 4; i += NTHR) {
          F4 yv = ld4(&sy[i * 4]);
          F4 s;
          {
            F4 k0 = ld4(&sk[i * 4]);
#pragma unroll
            for (int e = 0; e < 4; ++e) s.v[e] = cA[st - 1][0] * k0.v[e];
          }
#pragma unroll
          for (int j = 1; j < 6; ++j) {
            if (j < st) {
              F4 kv = ld4(&sk[j * TSZ + i * 4]);
#pragma unroll
              for (int e = 0; e < 4; ++e) s.v[e] = fmaf(cA[st - 1][j], kv.v[e], s.v[e]);
            }
          }
          F4 yiv;
#pragma unroll
          for (int e = 0; e < 4; ++e) yiv.v[e] = fmaf(h_eff, s.v[e], yv.v[e]);
          st4(&syi[i * 4], yiv);
          if (st == 6) st4(&Yo[base + i * 4], yiv);   /* candidate y5 */
        }
        __syncthreads();

        float acc[4][4];
        gemm64_f2(syi, sW2, rb4, cb, acc);

        if (st < 6) {
#pragma unroll
          for (int i = 0; i < 4; ++i) {
            F4 kv;
#pragma unroll
            for (int j = 0; j < 4; ++j) kv.v[j] = sinf(-(acc[i][j] + bb.v[j]));
            st4(&sk[st * TSZ + (rb4 + i) * DDIM + cb * 4], kv);
          }
          __syncthreads();
        } else {
#pragma unroll
          for (int i = 0; i < 4; ++i)
#pragma unroll
            for (int j = 0; j < 4; ++j) k7r[i][j] = sinf(-(acc[i][j] + bb.v[j]));
        }
      }

      /* error accumulation + FSAL k7 -> next k1 */
#pragma unroll
      for (int i = 0; i < 4; ++i) {
        const int o = (rb4 + i) * DDIM + cb * 4;
        F4 k1v = ld4(&sk[o]);
        F4 k3v = ld4(&sk[2 * TSZ + o]);
        F4 k4v = ld4(&sk[3 * TSZ + o]);
        F4 k5v = ld4(&sk[4 * TSZ + o]);
        F4 k6v = ld4(&sk[5 * TSZ + o]);
        F4 y5v = ld4(&syi[o]);
        F4 yv  = ld4(&sy[o]);
        F4 k7v;
#pragma unroll
        for (int j = 0; j < 4; ++j) k7v.v[j] = k7r[i][j];
        st4(&Ko[base + o], k7v);
#pragma unroll
        for (int j = 0; j < 4; ++j) {
          float e = E0 * k1v.v[j];
          e = fmaf(E2, k3v.v[j], e);
          e = fmaf(E3, k4v.v[j], e);
          e = fmaf(E4, k5v.v[j], e);
          e = fmaf(E5, k6v.v[j], e);
          e = fmaf(E6, k7v.v[j], e);
          e *= h_eff;
          float scale = fmaf(RTOL, fmaxf(fabsf(yv.v[j]), fabsf(y5v.v[j])), ATOL);
          float r = e / scale;
          lsum += (double)(r * r);
        }
      }
      __syncthreads();
    }

    /* deterministic block reduce (reuse sy region as doubles) */
    double* sdd = (double*)(sm + OFF_SY);
    sdd[tid] = lsum;
    __syncthreads();
#pragma unroll
    for (int off = NTHR / 2; off > 0; off >>= 1) {
      if (tid < off) sdd[tid] += sdd[tid + off];
      __syncthreads();
    }
    const int par = step & 1;
    if (tid == 0) g_part[par][bid] = sdd[0];

    /* grid barrier + fused control (thread 0 computes, smem broadcast) */
    ++nbar;
    if (tid == 0) {
      __threadfence();
      unsigned old = atomicAdd(&g_count, 1u);
      if (old == PBLK - 1) {
        atomicExch(&g_count, 0u);
        __threadfence();
        atomicExch(&g_release, nbar);
      } else {
        while (*((volatile unsigned*)&g_release) < nbar) { }
      }
      __threadfence();
      double s = 0.0;
      for (int i2 = 0; i2 < PBLK; ++i2) s += *((volatile double*)&g_part[par][i2]);
      sm[OFF_CTL] = sqrtf((float)(s / (double)((double)NROWS * (double)DDIM)));
    }
    __syncthreads();
    const float err_norm = sm[OFF_CTL];
    __syncthreads();

    /* exact reference control law, applied redundantly in every thread */
    const int accept = (err_norm <= 1.0f);
    if (accept) { t += h_eff; sel ^= 1; }
    float factor = 0.9f * powf(fmaxf(err_norm, 1e-10f), -0.2f);
    factor = fminf(fmaxf(factor, 0.2f), 10.0f);
    h = h_eff * factor;
    const float remaining = 5.0f - t;
    done = (remaining <= 0.0f) ? 1 : 0;
    h_eff = fminf(h, fmaxf(remaining, 1e-12f));
  }

  /* write accepted buffer to output (block-owned tiles) */
  const float* __restrict__ Yf = sel ? g_Yb : g_Ya;
  for (int tile = bid; tile < NTILE; tile += PBLK) {
    const size_t base = (size_t)tile * TSZ;
    for (int i = tid; i < TSZ / 4; i += NTHR)
      st4(&out[base + i * 4], ld4(&Yf[base + i * 4]));
  }
}

extern "C" void kernel_launch(void* const* d_in, const int* in_sizes, int n_in,
                              void* d_out, int out_size) {
  const float* x = (const float*)d_in[0];
  const float* W = (const float*)d_in[1];
  const float* b = (const float*)d_in[2];
  float* out = (float*)d_out;

  cudaFuncSetAttribute(ode_kernel, cudaFuncAttributeMaxDynamicSharedMemorySize, SMEM_BYTES);

  init_kernel<<<1, 1>>>();
  ode_kernel<<<PBLK, NTHR, SMEM_BYTES>>>(x, W, b, out);
}

// round 4
// speedup vs baseline: 1.5475x; 1.3315x over previous
#include <cuda_runtime.h>
#include <math.h>

#define NROWS   65536
#define DDIM    64
#define NTILE   1024          /* NROWS / 64 */
#define PBLK    148           /* persistent blocks, 1 per SM */
#define NTHR    512
#define NSTEPS  128
#define TSZ     4096          /* 64*64 floats per tile */

/* shared memory layout (float offsets) */
#define OFF_SB   0            /* 64   : bias                          */
#define OFF_CTL  64           /* 16   : control broadcast             */
#define OFF_W2   80           /* 4096 : W repacked (k-pair major)     */
#define OFF_SYI  4176         /* 4096 : stage input / y5 (+reduce)    */
#define OFF_SK2  8272         /* 5*4096 : k2..k6 (same-thread access) */
#define SMEM_FLOATS 28752
#define SMEM_BYTES  (SMEM_FLOATS * 4)

typedef unsigned long long ull;

/* ---------------- persistent device state (no allocations) ---------------- */
__device__ float  g_Ya[NROWS * DDIM];
__device__ float  g_Yb[NROWS * DDIM];
__device__ float  g_Ka[NROWS * DDIM];
__device__ float  g_Kb[NROWS * DDIM];
__device__ double g_part[2][PBLK];
__device__ unsigned g_count;
__device__ unsigned g_release;

/* Dormand-Prince A coefficients (exact float32 of rationals) */
__constant__ float cA[6][6] = {
  { (float)(1.0/5.0), 0.f, 0.f, 0.f, 0.f, 0.f },
  { (float)(3.0/40.0), (float)(9.0/40.0), 0.f, 0.f, 0.f, 0.f },
  { (float)(44.0/45.0), (float)(-56.0/15.0), (float)(32.0/9.0), 0.f, 0.f, 0.f },
  { (float)(19372.0/6561.0), (float)(-25360.0/2187.0), (float)(64448.0/6561.0), (float)(-212.0/729.0), 0.f, 0.f },
  { (float)(9017.0/3168.0), (float)(-355.0/33.0), (float)(46732.0/5247.0), (float)(49.0/176.0), (float)(-5103.0/18656.0), 0.f },
  { (float)(35.0/384.0), 0.f, (float)(500.0/1113.0), (float)(125.0/192.0), (float)(-2187.0/6784.0), (float)(11.0/84.0) },
};

struct F4 { float v[4]; };
__device__ __forceinline__ F4 ld4(const float* p) {
  float4 t = *(const float4*)p; F4 r; r.v[0]=t.x; r.v[1]=t.y; r.v[2]=t.z; r.v[3]=t.w; return r;
}
__device__ __forceinline__ void st4(float* p, const F4 a) {
  float4 t; t.x=a.v[0]; t.y=a.v[1]; t.z=a.v[2]; t.w=a.v[3]; *(float4*)p = t;
}

/* packed fp32x2 FMA (Blackwell) */
__device__ __forceinline__ ull fma2(ull a, ull b, ull c) {
  ull d;
  asm("fma.rn.f32x2 %0, %1, %2, %3;" : "=l"(d) : "l"(a), "l"(b), "l"(c));
  return d;
}
__device__ __forceinline__ void unpack2(ull v, float& lo, float& hi) {
  asm("mov.b64 {%0, %1}, %2;" : "=f"(lo), "=f"(hi) : "l"(v));
}

/* 2x4-output 64-k GEMM via fma.rn.f32x2.
   accf[i][j] = sum_k sa[r0+i][k] * W[cb*4+j][k]
   sW2 layout (from R3, validated): for k-pair k2 (0..31):
     sW2[k2*128 +      cb*4 + {0..3}] = {W[4cb][2k2],W[4cb][2k2+1],W[4cb+1][2k2],W[4cb+1][2k2+1]}
     sW2[k2*128 + 64 + cb*4 + {0..3}] = same for j=4cb+2, 4cb+3 */
__device__ __forceinline__ void gemm64_r2(const float* __restrict__ sa,
                                          const float* __restrict__ sW2,
                                          int r0, int cb, float accf[2][4]) {
  ull acc[2][4];
#pragma unroll
  for (int i = 0; i < 2; ++i)
#pragma unroll
    for (int j = 0; j < 4; ++j) acc[i][j] = 0ull;

#pragma unroll
  for (int k4 = 0; k4 < 16; ++k4) {
    ulonglong2 av[2];
#pragma unroll
    for (int i = 0; i < 2; ++i)
      av[i] = *(const ulonglong2*)(sa + (r0 + i) * DDIM + k4 * 4);
#pragma unroll
    for (int hh = 0; hh < 2; ++hh) {
      const int k2 = k4 * 2 + hh;
      ulonglong2 w01 = *(const ulonglong2*)(sW2 + k2 * 128 + cb * 4);
      ulonglong2 w23 = *(const ulonglong2*)(sW2 + k2 * 128 + 64 + cb * 4);
#pragma unroll
      for (int i = 0; i < 2; ++i) {
        ull a = hh ? av[i].y : av[i].x;
        acc[i][0] = fma2(a, w01.x, acc[i][0]);
        acc[i][1] = fma2(a, w01.y, acc[i][1]);
        acc[i][2] = fma2(a, w23.x, acc[i][2]);
        acc[i][3] = fma2(a, w23.y, acc[i][3]);
      }
    }
  }
#pragma unroll
  for (int i = 0; i < 2; ++i)
#pragma unroll
    for (int j = 0; j < 4; ++j) {
      float lo, hi; unpack2(acc[i][j], lo, hi);
      accf[i][j] = lo + hi;
    }
}

__global__ void init_kernel() { g_count = 0u; g_release = 0u; }

/* ---------------- the whole solve in one persistent kernel ---------------- */
__global__ void __launch_bounds__(NTHR, 1) ode_kernel(const float* __restrict__ x,
                                                      const float* __restrict__ W,
                                                      const float* __restrict__ b,
                                                      float* __restrict__ out) {
  extern __shared__ float sm[];
  float* sb  = sm + OFF_SB;
  float* sW2 = sm + OFF_W2;
  float* syi = sm + OFF_SYI;
  float* sk2 = sm + OFF_SK2;   /* slot m holds k_{m+2}, m=0..4; same-thread access only */

  const int tid = threadIdx.x, bid = blockIdx.x;
  const int r0 = (tid >> 4) << 1;   /* rows r0, r0+1 (0..62) */
  const int cb = tid & 15;          /* col group (j base = cb*4) */
  const int o0 = r0 * DDIM + cb * 4;       /* own element offsets */
  const int o1 = o0 + DDIM;

  if (tid < 16) st4(&sb[tid * 4], ld4(&b[tid * 4]));
  /* repack W into k-pair-major layout (validated in R3) */
  for (int p = tid; p < 2048; p += NTHR) {
    const int k2 = p >> 6, j = p & 63;
    const int cbb = j >> 2, jr = j & 3;
    const int pos = k2 * 128 + ((jr >= 2) ? 64 : 0) + cbb * 4 + (jr & 1) * 2;
    sW2[pos]     = W[j * DDIM + 2 * k2];
    sW2[pos + 1] = W[j * DDIM + 2 * k2 + 1];
  }
  __syncthreads();
  const F4 bb = ld4(&sb[cb * 4]);

  /* prologue: Ya = x ; Ka = k1 = f(x) */
  for (int tile = bid; tile < NTILE; tile += PBLK) {
    const size_t base = (size_t)tile * TSZ;
    for (int i = tid; i < TSZ / 4; i += NTHR) {
      F4 v = ld4(&x[base + i * 4]);
      st4(&syi[i * 4], v);
      st4(&g_Ya[base + i * 4], v);
    }
    __syncthreads();
    float acc[2][4];
    gemm64_r2(syi, sW2, r0, cb, acc);
#pragma unroll
    for (int i = 0; i < 2; ++i) {
      F4 kv;
#pragma unroll
      for (int j = 0; j < 4; ++j) kv.v[j] = sinf(-(acc[i][j] + bb.v[j]));
      st4(&g_Ka[base + (i ? o1 : o0)], kv);
    }
    __syncthreads();
  }

  float t = 0.0f, h = 0.01f, h_eff = 0.01f;
  int sel = 0, done = 0;
  unsigned nbar = 0;

  const float E0 = (float)(71.0 / 57600.0);
  const float E2 = (float)(-71.0 / 16695.0);
  const float E3 = (float)(71.0 / 1920.0);
  const float E4 = (float)(-17253.0 / 339200.0);
  const float E5 = (float)(22.0 / 525.0);
  const float E6 = (float)(-1.0 / 40.0);
  const float ATOL = 1e-5f, RTOL = 1e-5f;

  for (int step = 0; step < NSTEPS; ++step) {
    if (done) break;
    const float* __restrict__ Yg = sel ? g_Yb : g_Ya;
    const float* __restrict__ Kg = sel ? g_Kb : g_Ka;
    float* __restrict__ Yo = sel ? g_Ya : g_Yb;
    float* __restrict__ Ko = sel ? g_Ka : g_Kb;

    double lsum = 0.0;
    for (int tile = bid; tile < NTILE; tile += PBLK) {
      const size_t base = (size_t)tile * TSZ;
      /* own-element registers */
      F4 yv[2], k1v[2], k7v[2], y5v[2];
      yv[0]  = ld4(&Yg[base + o0]); yv[1]  = ld4(&Yg[base + o1]);
      k1v[0] = ld4(&Kg[base + o0]); k1v[1] = ld4(&Kg[base + o1]);

#pragma unroll
      for (int st = 1; st <= 6; ++st) {
        /* yi(own 8 elems) = y + h_eff*(A[st-1][0] k1 + sum_{m} A[st-1][m+1] k_{m+2}) */
#pragma unroll
        for (int i = 0; i < 2; ++i) {
          const int o = i ? o1 : o0;
          F4 s;
#pragma unroll
          for (int e = 0; e < 4; ++e) s.v[e] = cA[st - 1][0] * k1v[i].v[e];
#pragma unroll
          for (int m = 0; m < 5; ++m) {
            if (m + 2 <= st) {
              F4 kv = ld4(&sk2[m * TSZ + o]);
#pragma unroll
              for (int e = 0; e < 4; ++e) s.v[e] = fmaf(cA[st - 1][m + 1], kv.v[e], s.v[e]);
            }
          }
          F4 yiv;
#pragma unroll
          for (int e = 0; e < 4; ++e) yiv.v[e] = fmaf(h_eff, s.v[e], yv[i].v[e]);
          st4(&syi[o], yiv);
          if (st == 6) { y5v[i] = yiv; st4(&Yo[base + o], yiv); }
        }
        __syncthreads();

        float acc[2][4];
        gemm64_r2(syi, sW2, r0, cb, acc);

        if (st < 6) {
#pragma unroll
          for (int i = 0; i < 2; ++i) {
            F4 kv;
#pragma unroll
            for (int j = 0; j < 4; ++j) kv.v[j] = sinf(-(acc[i][j] + bb.v[j]));
            st4(&sk2[(st - 1) * TSZ + (i ? o1 : o0)], kv);  /* k_{st+1}, same-thread */
          }
        } else {
#pragma unroll
          for (int i = 0; i < 2; ++i)
#pragma unroll
            for (int j = 0; j < 4; ++j) k7v[i].v[j] = sinf(-(acc[i][j] + bb.v[j]));
        }
        __syncthreads();  /* WAR on syi before next stage / next tile */
      }

      /* error accumulation + FSAL k7 -> next k1 (all own-element) */
#pragma unroll
      for (int i = 0; i < 2; ++i) {
        const int o = i ? o1 : o0;
        F4 k3 = ld4(&sk2[1 * TSZ + o]);
        F4 k4 = ld4(&sk2[2 * TSZ + o]);
        F4 k5 = ld4(&sk2[3 * TSZ + o]);
        F4 k6 = ld4(&sk2[4 * TSZ + o]);
        st4(&Ko[base + o], k7v[i]);
#pragma unroll
        for (int j = 0; j < 4; ++j) {
          float e = E0 * k1v[i].v[j];
          e = fmaf(E2, k3.v[j], e);
          e = fmaf(E3, k4.v[j], e);
          e = fmaf(E4, k5.v[j], e);
          e = fmaf(E5, k6.v[j], e);
          e = fmaf(E6, k7v[i].v[j], e);
          e *= h_eff;
          float scale = fmaf(RTOL, fmaxf(fabsf(yv[i].v[j]), fabsf(y5v[i].v[j])), ATOL);
          float r = e / scale;
          lsum += (double)(r * r);
        }
      }
    }

    /* deterministic block reduce (reuse syi region as doubles) */
    __syncthreads();
    double* sdd = (double*)(sm + OFF_SYI);
    sdd[tid] = lsum;
    __syncthreads();
#pragma unroll
    for (int off = NTHR / 2; off > 0; off >>= 1) {
      if (tid < off) sdd[tid] += sdd[tid + off];
      __syncthreads();
    }
    const int par = step & 1;
    if (tid == 0) g_part[par][bid] = sdd[0];

    /* grid barrier + fused control */
    ++nbar;
    if (tid == 0) {
      __threadfence();
      unsigned old = atomicAdd(&g_count, 1u);
      if (old == PBLK - 1) {
        atomicExch(&g_count, 0u);
        __threadfence();
        atomicExch(&g_release, nbar);
      } else {
        while (*((volatile unsigned*)&g_release) < nbar) { }
      }
      __threadfence();
      double s = 0.0;
      for (int i2 = 0; i2 < PBLK; ++i2) s += *((volatile double*)&g_part[par][i2]);
      sm[OFF_CTL] = sqrtf((float)(s / (double)((double)NROWS * (double)DDIM)));
    }
    __syncthreads();
    const float err_norm = sm[OFF_CTL];
    __syncthreads();

    /* exact reference control law, applied redundantly in every thread */
    const int accept = (err_norm <= 1.0f);
    if (accept) { t += h_eff; sel ^= 1; }
    float factor = 0.9f * powf(fmaxf(err_norm, 1e-10f), -0.2f);
    factor = fminf(fmaxf(factor, 0.2f), 10.0f);
    h = h_eff * factor;
    const float remaining = 5.0f - t;
    done = (remaining <= 0.0f) ? 1 : 0;
    h_eff = fminf(h, fmaxf(remaining, 1e-12f));
  }

  /* write accepted buffer to output */
  const float* __restrict__ Yf = sel ? g_Yb : g_Ya;
  for (int tile = bid; tile < NTILE; tile += PBLK) {
    const size_t base = (size_t)tile * TSZ;
    for (int i = tid; i < TSZ / 4; i += NTHR)
      st4(&out[base + i * 4], ld4(&Yf[base + i * 4]));
  }
}

extern "C" void kernel_launch(void* const* d_in, const int* in_sizes, int n_in,
                              void* d_out, int out_size) {
  const float* x = (const float*)d_in[0];
  const float* W = (const float*)d_in[1];
  const float* b = (const float*)d_in[2];
  float* out = (float*)d_out;

  cudaFuncSetAttribute(ode_kernel, cudaFuncAttributeMaxDynamicSharedMemorySize, SMEM_BYTES);

  init_kernel<<<1, 1>>>();
  ode_kernel<<<PBLK, NTHR, SMEM_BYTES>>>(x, W, b, out);
}

// round 5
// speedup vs baseline: 2.1951x; 1.4185x over previous
#include <cuda_runtime.h>
#include <math.h>

#define NROWS   65536
#define DDIM    64
#define NTILE   1024          /* NROWS / 64 */
#define PBLK    148           /* persistent blocks, 1 per SM */
#define NTHR    512
#define NSTEPS  128
#define TSZ     4096          /* 64*64 floats per tile */

/* shared memory layout (float offsets) */
#define OFF_SB    0            /* 64   : bias                          */
#define OFF_CTL   64           /* 16   : control broadcast             */
#define OFF_W2    80           /* 4096 : W repacked (k-pair major)     */
#define OFF_SYI0  4176         /* 4096 : stage input buf 0 (+reduce)   */
#define OFF_SYI1  8272         /* 4096 : stage input buf 1             */
#define OFF_SK2   12368        /* 5*4096 : k2..k6 (same-thread access) */
#define SMEM_FLOATS 32848
#define SMEM_BYTES  (SMEM_FLOATS * 4)

typedef unsigned long long ull;

/* ---------------- persistent device state (no allocations) ---------------- */
__device__ float  g_Ya[NROWS * DDIM];
__device__ float  g_Yb[NROWS * DDIM];
__device__ float  g_Ka[NROWS * DDIM];
__device__ float  g_Kb[NROWS * DDIM];
__device__ double g_part[2][PBLK];
__device__ unsigned g_count;
__device__ unsigned g_release;

/* Dormand-Prince A coefficients (exact float32 of rationals) */
__constant__ float cA[6][6] = {
  { (float)(1.0/5.0), 0.f, 0.f, 0.f, 0.f, 0.f },
  { (float)(3.0/40.0), (float)(9.0/40.0), 0.f, 0.f, 0.f, 0.f },
  { (float)(44.0/45.0), (float)(-56.0/15.0), (float)(32.0/9.0), 0.f, 0.f, 0.f },
  { (float)(19372.0/6561.0), (float)(-25360.0/2187.0), (float)(64448.0/6561.0), (float)(-212.0/729.0), 0.f, 0.f },
  { (float)(9017.0/3168.0), (float)(-355.0/33.0), (float)(46732.0/5247.0), (float)(49.0/176.0), (float)(-5103.0/18656.0), 0.f },
  { (float)(35.0/384.0), 0.f, (float)(500.0/1113.0), (float)(125.0/192.0), (float)(-2187.0/6784.0), (float)(11.0/84.0) },
};

union F4U {
  float v[4];
  ull   q[2];
  float4 f4;
};

__device__ __forceinline__ F4U ld4u(const float* p) { F4U r; r.f4 = *(const float4*)p; return r; }
__device__ __forceinline__ void st4u(float* p, const F4U a) { *(float4*)p = a.f4; }

/* packed fp32x2 ops (Blackwell) */
__device__ __forceinline__ ull fma2(ull a, ull b, ull c) {
  ull d;
  asm("fma.rn.f32x2 %0, %1, %2, %3;" : "=l"(d) : "l"(a), "l"(b), "l"(c));
  return d;
}
__device__ __forceinline__ ull mul2(ull a, ull b) {
  ull d;
  asm("mul.rn.f32x2 %0, %1, %2;" : "=l"(d) : "l"(a), "l"(b));
  return d;
}
__device__ __forceinline__ ull pack2(float x) {
  ull d;
  asm("mov.b64 %0, {%1, %1};" : "=l"(d) : "f"(x));
  return d;
}
__device__ __forceinline__ void unpack2(ull v, float& lo, float& hi) {
  asm("mov.b64 {%0, %1}, %2;" : "=f"(lo), "=f"(hi) : "l"(v));
}

/* fast sin: arguments here are O(1..10), sin.approx abs error ~2^-21 —
   3 orders of magnitude below the 1e-3 output tolerance. */
__device__ __forceinline__ float fsin(float x) {
  float r;
  asm("sin.approx.f32 %0, %1;" : "=f"(r) : "f"(x));
  return r;
}

/* 2x4-output 64-k GEMM via fma.rn.f32x2 (layout validated in R3/R4). */
__device__ __forceinline__ void gemm64_r2(const float* __restrict__ sa,
                                          const float* __restrict__ sW2,
                                          int r0, int cb, float accf[2][4]) {
  ull acc[2][4];
#pragma unroll
  for (int i = 0; i < 2; ++i)
#pragma unroll
    for (int j = 0; j < 4; ++j) acc[i][j] = 0ull;

#pragma unroll
  for (int k4 = 0; k4 < 16; ++k4) {
    ulonglong2 av[2];
#pragma unroll
    for (int i = 0; i < 2; ++i)
      av[i] = *(const ulonglong2*)(sa + (r0 + i) * DDIM + k4 * 4);
#pragma unroll
    for (int hh = 0; hh < 2; ++hh) {
      const int k2 = k4 * 2 + hh;
      ulonglong2 w01 = *(const ulonglong2*)(sW2 + k2 * 128 + cb * 4);
      ulonglong2 w23 = *(const ulonglong2*)(sW2 + k2 * 128 + 64 + cb * 4);
#pragma unroll
      for (int i = 0; i < 2; ++i) {
        ull a = hh ? av[i].y : av[i].x;
        acc[i][0] = fma2(a, w01.x, acc[i][0]);
        acc[i][1] = fma2(a, w01.y, acc[i][1]);
        acc[i][2] = fma2(a, w23.x, acc[i][2]);
        acc[i][3] = fma2(a, w23.y, acc[i][3]);
      }
    }
  }
#pragma unroll
  for (int i = 0; i < 2; ++i)
#pragma unroll
    for (int j = 0; j < 4; ++j) {
      float lo, hi; unpack2(acc[i][j], lo, hi);
      accf[i][j] = lo + hi;
    }
}

__global__ void init_kernel() { g_count = 0u; g_release = 0u; }

/* ---------------- the whole solve in one persistent kernel ---------------- */
__global__ void __launch_bounds__(NTHR, 1) ode_kernel(const float* __restrict__ x,
                                                      const float* __restrict__ W,
                                                      const float* __restrict__ b,
                                                      float* __restrict__ out) {
  extern __shared__ float sm[];
  float* sb   = sm + OFF_SB;
  float* sW2  = sm + OFF_W2;
  float* syi0 = sm + OFF_SYI0;
  float* syi1 = sm + OFF_SYI1;
  float* sk2  = sm + OFF_SK2;  /* slot m holds k_{m+2}; same-thread access only */

  const int tid = threadIdx.x, bid = blockIdx.x;
  const int r0 = (tid >> 4) << 1;       /* rows r0, r0+1 */
  const int cb = tid & 15;              /* col group j = cb*4 .. cb*4+3 */
  const int o0 = r0 * DDIM + cb * 4;
  const int o1 = o0 + DDIM;

  if (tid < 16) st4u(&sb[tid * 4], ld4u(&b[tid * 4]));
  /* repack W into k-pair-major layout */
  for (int p = tid; p < 2048; p += NTHR) {
    const int k2 = p >> 6, j = p & 63;
    const int cbb = j >> 2, jr = j & 3;
    const int pos = k2 * 128 + ((jr >= 2) ? 64 : 0) + cbb * 4 + (jr & 1) * 2;
    sW2[pos]     = W[j * DDIM + 2 * k2];
    sW2[pos + 1] = W[j * DDIM + 2 * k2 + 1];
  }
  __syncthreads();
  const F4U bb = ld4u(&sb[cb * 4]);

  /* prologue: Ya = x ; Ka = k1 = f(x) */
  for (int tile = bid; tile < NTILE; tile += PBLK) {
    const size_t base = (size_t)tile * TSZ;
    for (int i = tid; i < TSZ / 4; i += NTHR) {
      F4U v = ld4u(&x[base + i * 4]);
      st4u(&syi0[i * 4], v);
      st4u(&g_Ya[base + i * 4], v);
    }
    __syncthreads();
    float acc[2][4];
    gemm64_r2(syi0, sW2, r0, cb, acc);
#pragma unroll
    for (int i = 0; i < 2; ++i) {
      F4U kv;
#pragma unroll
      for (int j = 0; j < 4; ++j) kv.v[j] = fsin(-(acc[i][j] + bb.v[j]));
      st4u(&g_Ka[base + (i ? o1 : o0)], kv);
    }
    __syncthreads();
  }

  float t = 0.0f, h = 0.01f, h_eff = 0.01f;
  int sel = 0, done = 0;
  unsigned nbar = 0;

  const float E0 = (float)(71.0 / 57600.0);
  const float E2 = (float)(-71.0 / 16695.0);
  const float E3 = (float)(71.0 / 1920.0);
  const float E4 = (float)(-17253.0 / 339200.0);
  const float E5 = (float)(22.0 / 525.0);
  const float E6 = (float)(-1.0 / 40.0);
  const float ATOL = 1e-5f, RTOL = 1e-5f;

  for (int step = 0; step < NSTEPS; ++step) {
    if (done) break;
    const float* __restrict__ Yg = sel ? g_Yb : g_Ya;
    const float* __restrict__ Kg = sel ? g_Kb : g_Ka;
    float* __restrict__ Yo = sel ? g_Ya : g_Yb;
    float* __restrict__ Ko = sel ? g_Ka : g_Kb;
    const ull h2 = pack2(h_eff);

    double lsum = 0.0;
    for (int tile = bid; tile < NTILE; tile += PBLK) {
      const size_t base = (size_t)tile * TSZ;
      F4U yv[2], k1v[2], k7v[2], y5v[2];
      yv[0]  = ld4u(&Yg[base + o0]); yv[1]  = ld4u(&Yg[base + o1]);
      k1v[0] = ld4u(&Kg[base + o0]); k1v[1] = ld4u(&Kg[base + o1]);

#pragma unroll
      for (int st = 1; st <= 6; ++st) {
        float* syiW = (st & 1) ? syi1 : syi0;
        /* packed coefficients for this stage */
        const ull c1 = pack2(cA[st - 1][0]);
        /* yi = y + h*(c1*k1 + sum_m c_{m+2} * k_{m+2}) on own 8 elems */
#pragma unroll
        for (int i = 0; i < 2; ++i) {
          const int o = i ? o1 : o0;
          ull s0 = mul2(c1, k1v[i].q[0]);
          ull s1 = mul2(c1, k1v[i].q[1]);
#pragma unroll
          for (int m = 0; m < 5; ++m) {
            if (m + 2 <= st) {
              const ull cm = pack2(cA[st - 1][m + 1]);
              F4U kv = ld4u(&sk2[m * TSZ + o]);
              s0 = fma2(cm, kv.q[0], s0);
              s1 = fma2(cm, kv.q[1], s1);
            }
          }
          F4U yiv;
          yiv.q[0] = fma2(h2, s0, yv[i].q[0]);
          yiv.q[1] = fma2(h2, s1, yv[i].q[1]);
          st4u(&syiW[o], yiv);
          if (st == 6) { y5v[i] = yiv; st4u(&Yo[base + o], yiv); }
        }
        __syncthreads();   /* single sync: writes of buf visible before reads */

        float acc[2][4];
        gemm64_r2(syiW, sW2, r0, cb, acc);

        if (st < 6) {
#pragma unroll
          for (int i = 0; i < 2; ++i) {
            F4U kv;
#pragma unroll
            for (int j = 0; j < 4; ++j) kv.v[j] = fsin(-(acc[i][j] + bb.v[j]));
            st4u(&sk2[(st - 1) * TSZ + (i ? o1 : o0)], kv);  /* same-thread */
          }
        } else {
#pragma unroll
          for (int i = 0; i < 2; ++i)
#pragma unroll
            for (int j = 0; j < 4; ++j) k7v[i].v[j] = fsin(-(acc[i][j] + bb.v[j]));
        }
        /* no second sync: stage st+2 writes this buffer only after the
           sync inside stage st+1 */
      }

      /* error accumulation + FSAL k7 -> next k1 (own-element only) */
#pragma unroll
      for (int i = 0; i < 2; ++i) {
        const int o = i ? o1 : o0;
        F4U k3 = ld4u(&sk2[1 * TSZ + o]);
        F4U k4 = ld4u(&sk2[2 * TSZ + o]);
        F4U k5 = ld4u(&sk2[3 * TSZ + o]);
        F4U k6 = ld4u(&sk2[4 * TSZ + o]);
        st4u(&Ko[base + o], k7v[i]);
#pragma unroll
        for (int j = 0; j < 4; ++j) {
          float e = E0 * k1v[i].v[j];
          e = fmaf(E2, k3.v[j], e);
          e = fmaf(E3, k4.v[j], e);
          e = fmaf(E4, k5.v[j], e);
          e = fmaf(E5, k6.v[j], e);
          e = fmaf(E6, k7v[i].v[j], e);
          e *= h_eff;
          float scale = fmaf(RTOL, fmaxf(fabsf(yv[i].v[j]), fabsf(y5v[i].v[j])), ATOL);
          float r = e / scale;
          lsum += (double)(r * r);
        }
      }
      __syncthreads();   /* protect syi0 (y5 buffer) before next tile reuse */
    }

    /* deterministic block reduce (reuse syi0 region as doubles) */
    double* sdd = (double*)(sm + OFF_SYI0);
    sdd[tid] = lsum;
    __syncthreads();
#pragma unroll
    for (int off = NTHR / 2; off > 0; off >>= 1) {
      if (tid < off) sdd[tid] += sdd[tid + off];
      __syncthreads();
    }
    const int par = step & 1;
    if (tid == 0) g_part[par][bid] = sdd[0];

    /* grid barrier + fused control */
    ++nbar;
    if (tid == 0) {
      __threadfence();
      unsigned old = atomicAdd(&g_count, 1u);
      if (old == PBLK - 1) {
        atomicExch(&g_count, 0u);
        __threadfence();
        atomicExch(&g_release, nbar);
      } else {
        while (*((volatile unsigned*)&g_release) < nbar) { }
      }
      __threadfence();
      double s = 0.0;
      for (int i2 = 0; i2 < PBLK; ++i2) s += *((volatile double*)&g_part[par][i2]);
      sm[OFF_CTL] = sqrtf((float)(s / (double)((double)NROWS * (double)DDIM)));
    }
    __syncthreads();
    const float err_norm = sm[OFF_CTL];
    __syncthreads();

    /* exact reference control law (redundant in every thread) */
    const int accept = (err_norm <= 1.0f);
    if (accept) { t += h_eff; sel ^= 1; }
    float factor = 0.9f * powf(fmaxf(err_norm, 1e-10f), -0.2f);
    factor = fminf(fmaxf(factor, 0.2f), 10.0f);
    h = h_eff * factor;
    const float remaining = 5.0f - t;
    done = (remaining <= 0.0f) ? 1 : 0;
    h_eff = fminf(h, fmaxf(remaining, 1e-12f));
  }

  /* write accepted buffer to output */
  const float* __restrict__ Yf = sel ? g_Yb : g_Ya;
  for (int tile = bid; tile < NTILE; tile += PBLK) {
    const size_t base = (size_t)tile * TSZ;
    for (int i = tid; i < TSZ / 4; i += NTHR)
      st4u(&out[base + i * 4], ld4u(&Yf[base + i * 4]));
  }
}

extern "C" void kernel_launch(void* const* d_in, const int* in_sizes, int n_in,
                              void* d_out, int out_size) {
  const float* x = (const float*)d_in[0];
  const float* W = (const float*)d_in[1];
  const float* b = (const float*)d_in[2];
  float* out = (float*)d_out;

  cudaFuncSetAttribute(ode_kernel, cudaFuncAttributeMaxDynamicSharedMemorySize, SMEM_BYTES);

  init_kernel<<<1, 1>>>();
  ode_kernel<<<PBLK, NTHR, SMEM_BYTES>>>(x, W, b, out);
}